// round 15
// baseline (speedup 1.0000x reference)
#include <cuda_runtime.h>
#include <cuda_fp16.h>
#include <cstdint>
#include <cstddef>

// Problem dims
#define M_DIM 8192
#define N_DIM 4096
#define K_DIM 4096

// Tiling: CTA tile 128x128, K-step 64 fp16 = 128B rows (sw128), 2 CTAs/SM.
#define M_TILES 64
#define N_TILES 32
#define K_TILES 64
#define STAGES 3
#define BLK_BYTES 16384               // one 128x64 fp16 block
#define STAGE_BYTES (2 * BLK_BYTES)   // A | B
#define OFF_SCAL (STAGES * STAGE_BYTES)
#define SMEM_BYTES (OFF_SCAL + 1024)  // 99328 B -> 2 CTAs fit in 228KB

// Packed, pre-swizzled global scratch (allocation-free: __device__ globals)
static __device__ __align__(1024) __half g_w [(size_t)N_DIM * K_DIM];
static __device__ __align__(1024) __half g_x [(size_t)M_DIM * K_DIM];

__device__ __forceinline__ uint32_t sw128(uint32_t off) {
    return off ^ ((off >> 3) & 0x70u);
}

__device__ __forceinline__ uint32_t smem_u32(const void* p) {
    uint32_t a;
    asm("{ .reg .u64 t; cvta.to.shared.u64 t, %1; cvt.u32.u64 %0, t; }" : "=r"(a) : "l"(p));
    return a;
}

// fp16 convert + pack: low 16 bits = element at LOWER k (little-endian order).
__device__ __forceinline__ uint32_t pack_half(float even_k, float odd_k) {
    __half h0 = __float2half_rn(even_k);
    __half h1 = __float2half_rn(odd_k);
    uint16_t u0 = *(const uint16_t*)&h0;
    uint16_t u1 = *(const uint16_t*)&h1;
    return (uint32_t)u0 | ((uint32_t)u1 << 16);
}

__device__ __forceinline__ void cp16(uint32_t dst, const void* src) {
    asm volatile("cp.async.cg.shared.global [%0], [%1], 16;" :: "r"(dst), "l"(src));
}

__device__ __forceinline__ void ldsm4(uint32_t* r, uint32_t addr) {
    asm volatile("ldmatrix.sync.aligned.m8n8.x4.shared.b16 {%0,%1,%2,%3}, [%4];"
        : "=r"(r[0]), "=r"(r[1]), "=r"(r[2]), "=r"(r[3]) : "r"(addr) : "memory");
}

__device__ __forceinline__ void mma16816(float* c, const uint32_t* a, uint32_t b0, uint32_t b1) {
    asm volatile("mma.sync.aligned.m16n8k16.row.col.f32.f16.f16.f32 "
        "{%0,%1,%2,%3}, {%4,%5,%6,%7}, {%8,%9}, {%0,%1,%2,%3};"
        : "+f"(c[0]), "+f"(c[1]), "+f"(c[2]), "+f"(c[3])
        : "r"(a[0]), "r"(a[1]), "r"(a[2]), "r"(a[3]), "r"(b0), "r"(b1));
}

// ---------------------------------------------------------------------------
// Merged prologue: blocks [0,4096) convert INT32 weight -> fp16 (exact),
// blocks [4096,20480) convert fp32 x -> fp16. Both tile-major + sw128
// pre-swizzled. W block id = k_tile*32 + n_blk ; A block id = m_blk*64 + k_tile.
// ---------------------------------------------------------------------------
__global__ __launch_bounds__(256)
void conv_all_kernel(const int* __restrict__ w, const float* __restrict__ x) {
    if (blockIdx.x < 4096) {
        int idx = blockIdx.x * blockDim.x + threadIdx.x;     // 0 .. 1048575
        int n  = idx >> 8;
        int kc = (idx & 255) << 4;                           // 16 values per thread
        const int4* src = (const int4*)(w + (size_t)n * K_DIM + kc);
        int4 v0 = src[0], v1 = src[1], v2 = src[2], v3 = src[3];
        int vals[16] = { v0.x, v0.y, v0.z, v0.w, v1.x, v1.y, v1.z, v1.w,
                         v2.x, v2.y, v2.z, v2.w, v3.x, v3.y, v3.z, v3.w };
        uint32_t o[8];
#pragma unroll
        for (int i = 0; i < 8; i++)
            o[i] = pack_half((float)vals[2*i], (float)vals[2*i+1]);
        int n_blk = n >> 7, r = n & 127, k_tile = kc >> 6, c = kc & 63;
        size_t blk = (size_t)(k_tile * 32 + n_blk) * BLK_BYTES;
        uint32_t off = (uint32_t)(r * 128 + c * 2);
        *(uint4*)((char*)g_w + blk + sw128(off))      = make_uint4(o[0], o[1], o[2], o[3]);
        *(uint4*)((char*)g_w + blk + sw128(off + 16)) = make_uint4(o[4], o[5], o[6], o[7]);
    } else {
        int idx = (blockIdx.x - 4096) * blockDim.x + threadIdx.x;  // 0 .. 4194303
        int m  = idx >> 9;
        int k8 = (idx & 511) << 3;                           // 8 floats per thread
        const float4* p = (const float4*)(x + (size_t)m * K_DIM + k8);
        float4 a = p[0], b = p[1];
        float f[8] = {a.x, a.y, a.z, a.w, b.x, b.y, b.z, b.w};
        uint32_t o[4];
#pragma unroll
        for (int i = 0; i < 4; i++)
            o[i] = pack_half(f[2*i], f[2*i+1]);
        int m_blk = m >> 7, r = m & 127, k_tile = k8 >> 6, c = k8 & 63;
        size_t base = (size_t)(m_blk * 64 + k_tile) * BLK_BYTES
                    + sw128((uint32_t)(r * 128 + c * 2));
        *(uint4*)((char*)g_x + base) = make_uint4(o[0], o[1], o[2], o[3]);
    }
}

// ---------------------------------------------------------------------------
// Main GEMM: 3-stage cp.async + fp16 HMMA. CTA 128x128, 256 threads,
// warp grid 4(m)x2(n), warp tile 32x64, 2 CTAs per SM (proven R14 frame).
// R15 change: ROTATING SOFTWARE PIPELINE inside each K-tile. All ldsm/mma are
// asm volatile (order frozen), so the next k16's ldsm are interleaved into the
// current k16's HMMA stream: each B quad q[p] is overwritten immediately after
// its last reader (WAR, scoreboard-safe, zero extra regs); A frags are double-
// buffered (+8 regs, ~122 total, still 2 CTAs/SM). Exposed ldsm walls per kt
// drop from 4 to 1 (post-sync prologue).
// ldmatrix addressing: row = lane&15, half = (lane>>4)*16, xor = (lane&7)<<4.
// B pair for n8 block nt of quad q[nt>>1]: {q[nt&1], q[(nt&1)+2]}.
// ---------------------------------------------------------------------------
__global__ __launch_bounds__(256, 2)
void gemm_kernel(float* __restrict__ out, const float* __restrict__ scaler) {
    extern __shared__ __align__(1024) char smem[];
    uint32_t sbase = smem_u32(smem);
    int tid = threadIdx.x, lane = tid & 31, wid = tid >> 5;
    int n_tile = blockIdx.x & 31, m_tile = blockIdx.x >> 5;   // n fastest: W stays L2-hot
    int warp_m = wid & 3, warp_n = wid >> 2;

    if (tid < 128)
        ((float*)(smem + OFF_SCAL))[tid] = scaler[n_tile * 128 + tid];

    const char* gA = (const char*)g_x + (size_t)(m_tile * 64) * BLK_BYTES;
    const char* gB = (const char*)g_w + (size_t)n_tile * BLK_BYTES;

    int r16 = lane & 15;
    uint32_t bytesel = (uint32_t)((lane >> 4) * 16);
    uint32_t rxor    = (uint32_t)((lane & 7) << 4);
    uint32_t a_off[2], b_off[4];
#pragma unroll
    for (int mt = 0; mt < 2; mt++)
        a_off[mt] = (uint32_t)((warp_m * 32 + mt * 16 + r16) * 128);
#pragma unroll
    for (int p = 0; p < 4; p++)
        b_off[p] = (uint32_t)((warp_n * 64 + p * 16 + r16) * 128);

    float c[2][8][4];
#pragma unroll
    for (int mt = 0; mt < 2; mt++)
#pragma unroll
        for (int nt = 0; nt < 8; nt++)
#pragma unroll
            for (int j = 0; j < 4; j++) c[mt][nt][j] = 0.f;

    auto load_stage = [&](int s, int kt) {
        uint32_t dst = sbase + (uint32_t)s * STAGE_BYTES;
        const char* sA = gA + (size_t)kt * BLK_BYTES;
        const char* sB = gB + (size_t)kt * (32 * BLK_BYTES);
#pragma unroll
        for (int r = 0; r < 4; r++) {
            uint32_t off = (uint32_t)((r * 256 + tid) * 16);
            cp16(dst + off,             sA + off);
            cp16(dst + BLK_BYTES + off, sB + off);
        }
        asm volatile("cp.async.commit_group;" ::: "memory");
    };

    load_stage(0, 0);
    load_stage(1, 1);            // pending = {kt0, kt1}

    // Fragment registers: B quads rotated in place, A double-buffered.
    uint32_t q[4][4], av[2][2][4];

    for (int t = 0; t < K_TILES; t++) {
        // Entry invariant: pending = {kt t, kt t+1} (or just {kt t} at the tail).
        if (t < K_TILES - 1)
            asm volatile("cp.async.wait_group 1;" ::: "memory");  // kt t landed
        else
            asm volatile("cp.async.wait_group 0;" ::: "memory");
        __syncthreads();                 // all warps done reading stage (t-1)%3

        // Refill the stage freed by the sync: kt t+2 -> stage (t+2)%3 == (t-1)%3.
        if (t + 2 < K_TILES) load_stage((t + 2) % STAGES, t + 2);

        uint32_t st = sbase + (uint32_t)(t % STAGES) * STAGE_BYTES;
        uint32_t aBs = st, bBs = st + BLK_BYTES;

        // kt prologue: k16=0 fragments (the one exposed ldsm wall per kt).
        {
            uint32_t low = bytesel ^ rxor;
            ldsm4(q[0],     bBs + b_off[0] + low);
            ldsm4(av[0][0], aBs + a_off[0] + low);
            ldsm4(av[0][1], aBs + a_off[1] + low);
            ldsm4(q[1],     bBs + b_off[1] + low);
            ldsm4(q[2],     bBs + b_off[2] + low);
            ldsm4(q[3],     bBs + b_off[3] + low);
        }

#pragma unroll
        for (int k16 = 0; k16 < 4; k16++) {
            const int cb = k16 & 1, nb = cb ^ 1;
            const bool pf = (k16 < 3);
            uint32_t lowN = ((uint32_t)((k16 + 1) * 32) | bytesel) ^ rxor;

            // nt = 0,1  (quad q[0]) ; then q[0] <- next k16 (WAR rotate)
            mma16816(c[0][0], av[cb][0], q[0][0], q[0][2]);
            mma16816(c[1][0], av[cb][1], q[0][0], q[0][2]);
            mma16816(c[0][1], av[cb][0], q[0][1], q[0][3]);
            mma16816(c[1][1], av[cb][1], q[0][1], q[0][3]);
            if (pf) ldsm4(q[0], bBs + b_off[0] + lowN);

            // nt = 2,3  (quad q[1])
            mma16816(c[0][2], av[cb][0], q[1][0], q[1][2]);
            mma16816(c[1][2], av[cb][1], q[1][0], q[1][2]);
            mma16816(c[0][3], av[cb][0], q[1][1], q[1][3]);
            mma16816(c[1][3], av[cb][1], q[1][1], q[1][3]);
            if (pf) ldsm4(q[1], bBs + b_off[1] + lowN);

            // nt = 4,5  (quad q[2]) ; also prefetch next A (double buffer)
            mma16816(c[0][4], av[cb][0], q[2][0], q[2][2]);
            mma16816(c[1][4], av[cb][1], q[2][0], q[2][2]);
            mma16816(c[0][5], av[cb][0], q[2][1], q[2][3]);
            mma16816(c[1][5], av[cb][1], q[2][1], q[2][3]);
            if (pf) {
                ldsm4(q[2],     bBs + b_off[2] + lowN);
                ldsm4(av[nb][0], aBs + a_off[0] + lowN);
                ldsm4(av[nb][1], aBs + a_off[1] + lowN);
            }

            // nt = 6,7  (quad q[3]; last readers of av[cb])
            mma16816(c[0][6], av[cb][0], q[3][0], q[3][2]);
            mma16816(c[1][6], av[cb][1], q[3][0], q[3][2]);
            mma16816(c[0][7], av[cb][0], q[3][1], q[3][3]);
            mma16816(c[1][7], av[cb][1], q[3][1], q[3][3]);
            if (pf) ldsm4(q[3], bBs + b_off[3] + lowN);
        }
    }

    // Epilogue: scale by per-output-channel weight_scaler, write fp32
    const float* scl = (const float*)(smem + OFF_SCAL);
    int lr = lane >> 2, lc = (lane & 3) * 2;
#pragma unroll
    for (int mt = 0; mt < 2; mt++) {
        int row = m_tile * 128 + warp_m * 32 + mt * 16 + lr;
#pragma unroll
        for (int nt = 0; nt < 8; nt++) {
            int cloc = warp_n * 64 + nt * 8 + lc;
            float s0 = scl[cloc], s1 = scl[cloc + 1];
            size_t g0 = (size_t)row * N_DIM + (size_t)(n_tile * 128 + cloc);
            float2 v0 = make_float2(c[mt][nt][0] * s0, c[mt][nt][1] * s1);
            float2 v1 = make_float2(c[mt][nt][2] * s0, c[mt][nt][3] * s1);
            *(float2*)(out + g0)                     = v0;
            *(float2*)(out + g0 + 8 * (size_t)N_DIM) = v1;
        }
    }
}

// ---------------------------------------------------------------------------
extern "C" void kernel_launch(void* const* d_in, const int* in_sizes, int n_in,
                              void* d_out, int out_size) {
    // Size-based input resolution: x 33554432, weight 16777216, scaler 4096
    const float* x  = 0;
    const int*   w  = 0;
    const float* ws = 0;
    for (int i = 0; i < n_in; i++) {
        if (in_sizes[i] == 33554432)      x  = (const float*)d_in[i];
        else if (in_sizes[i] == 16777216) w  = (const int*)d_in[i];
        else if (in_sizes[i] == 4096)     ws = (const float*)d_in[i];
    }
    float* o = (float*)d_out;

    cudaFuncSetAttribute(gemm_kernel, cudaFuncAttributeMaxDynamicSharedMemorySize, SMEM_BYTES);

    conv_all_kernel<<<20480, 256>>>(w, x);
    gemm_kernel<<<M_TILES * N_TILES, 256, SMEM_BYTES>>>(o, ws);
}

// round 17
// speedup vs baseline: 1.0775x; 1.0775x over previous
#include <cuda_runtime.h>
#include <cuda_fp16.h>
#include <cstdint>
#include <cstddef>

// Problem dims
#define M_DIM 8192
#define N_DIM 4096
#define K_DIM 4096

// Tiling: CTA tile 64(m) x 128(n), K-step 64 fp16 = 128B rows (sw128).
// 128 threads = 4 warps, warp grid 2(m) x 2(n), warp tile 32x64.
// 4 CTAs per SM -> 4 independent barrier domains (R11: 1 dom = 60.0% tensor,
// R14: 2 doms = 64.5%; this tests 4 doms with a CORRECT 2-stage pipeline).
#define M_TILES 128            // 8192/64
#define N_TILES 32             // 4096/128
#define K_TILES 64
#define STAGES 2
#define A_SLICE_BYTES 8192     // 64 rows x 128B
#define B_BLK_BYTES 16384      // 128 rows x 128B
#define STAGE_BYTES (A_SLICE_BYTES + B_BLK_BYTES)   // 24KB
#define OFF_SCAL (STAGES * STAGE_BYTES)
#define SMEM_BYTES (OFF_SCAL + 1024)   // ~49.5KB -> 4 CTAs = 198KB <= 228KB

// Packed, pre-swizzled global scratch (allocation-free: __device__ globals)
// Layouts IDENTICAL to the verified R14 kernel.
static __device__ __align__(1024) __half g_w [(size_t)N_DIM * K_DIM];
static __device__ __align__(1024) __half g_x [(size_t)M_DIM * K_DIM];

__device__ __forceinline__ uint32_t sw128(uint32_t off) {
    return off ^ ((off >> 3) & 0x70u);
}

__device__ __forceinline__ uint32_t smem_u32(const void* p) {
    uint32_t a;
    asm("{ .reg .u64 t; cvta.to.shared.u64 t, %1; cvt.u32.u64 %0, t; }" : "=r"(a) : "l"(p));
    return a;
}

// fp16 convert + pack: low 16 bits = element at LOWER k (little-endian order).
__device__ __forceinline__ uint32_t pack_half(float even_k, float odd_k) {
    __half h0 = __float2half_rn(even_k);
    __half h1 = __float2half_rn(odd_k);
    uint16_t u0 = *(const uint16_t*)&h0;
    uint16_t u1 = *(const uint16_t*)&h1;
    return (uint32_t)u0 | ((uint32_t)u1 << 16);
}

__device__ __forceinline__ void cp16(uint32_t dst, const void* src) {
    asm volatile("cp.async.cg.shared.global [%0], [%1], 16;" :: "r"(dst), "l"(src));
}

__device__ __forceinline__ void ldsm4(uint32_t* r, uint32_t addr) {
    asm volatile("ldmatrix.sync.aligned.m8n8.x4.shared.b16 {%0,%1,%2,%3}, [%4];"
        : "=r"(r[0]), "=r"(r[1]), "=r"(r[2]), "=r"(r[3]) : "r"(addr) : "memory");
}

__device__ __forceinline__ void mma16816(float* c, const uint32_t* a, uint32_t b0, uint32_t b1) {
    asm volatile("mma.sync.aligned.m16n8k16.row.col.f32.f16.f16.f32 "
        "{%0,%1,%2,%3}, {%4,%5,%6,%7}, {%8,%9}, {%0,%1,%2,%3};"
        : "+f"(c[0]), "+f"(c[1]), "+f"(c[2]), "+f"(c[3])
        : "r"(a[0]), "r"(a[1]), "r"(a[2]), "r"(a[3]), "r"(b0), "r"(b1));
}

// ---------------------------------------------------------------------------
// Merged prologue: blocks [0,4096) convert INT32 weight -> fp16 (exact),
// blocks [4096,20480) convert fp32 x -> fp16. Both tile-major + sw128
// pre-swizzled. W block id = k_tile*32 + n_blk ; A block id = m_blk*64 + k_tile.
// (Byte-identical to the verified R14 prologue.)
// ---------------------------------------------------------------------------
__global__ __launch_bounds__(256)
void conv_all_kernel(const int* __restrict__ w, const float* __restrict__ x) {
    if (blockIdx.x < 4096) {
        int idx = blockIdx.x * blockDim.x + threadIdx.x;     // 0 .. 1048575
        int n  = idx >> 8;
        int kc = (idx & 255) << 4;                           // 16 values per thread
        const int4* src = (const int4*)(w + (size_t)n * K_DIM + kc);
        int4 v0 = src[0], v1 = src[1], v2 = src[2], v3 = src[3];
        int vals[16] = { v0.x, v0.y, v0.z, v0.w, v1.x, v1.y, v1.z, v1.w,
                         v2.x, v2.y, v2.z, v2.w, v3.x, v3.y, v3.z, v3.w };
        uint32_t o[8];
#pragma unroll
        for (int i = 0; i < 8; i++)
            o[i] = pack_half((float)vals[2*i], (float)vals[2*i+1]);
        int n_blk = n >> 7, r = n & 127, k_tile = kc >> 6, c = kc & 63;
        size_t blk = (size_t)(k_tile * 32 + n_blk) * B_BLK_BYTES;
        uint32_t off = (uint32_t)(r * 128 + c * 2);
        *(uint4*)((char*)g_w + blk + sw128(off))      = make_uint4(o[0], o[1], o[2], o[3]);
        *(uint4*)((char*)g_w + blk + sw128(off + 16)) = make_uint4(o[4], o[5], o[6], o[7]);
    } else {
        int idx = (blockIdx.x - 4096) * blockDim.x + threadIdx.x;  // 0 .. 4194303
        int m  = idx >> 9;
        int k8 = (idx & 511) << 3;                           // 8 floats per thread
        const float4* p = (const float4*)(x + (size_t)m * K_DIM + k8);
        float4 a = p[0], b = p[1];
        float f[8] = {a.x, a.y, a.z, a.w, b.x, b.y, b.z, b.w};
        uint32_t o[4];
#pragma unroll
        for (int i = 0; i < 4; i++)
            o[i] = pack_half(f[2*i], f[2*i+1]);
        int m_blk = m >> 7, r = m & 127, k_tile = k8 >> 6, c = k8 & 63;
        size_t base = (size_t)(m_blk * 64 + k_tile) * B_BLK_BYTES
                    + sw128((uint32_t)(r * 128 + c * 2));
        *(uint4*)((char*)g_x + base) = make_uint4(o[0], o[1], o[2], o[3]);
    }
}

// ---------------------------------------------------------------------------
// Main GEMM: 2-stage cp.async + fp16 HMMA. CTA 64x128, 128 threads,
// warp grid 2(m)x2(n), warp tile 32x64, 4 CTAs/SM.
// R17 FIX vs R16: cp.async.wait_group is PER-THREAD -- a thread's wait says
// nothing about other threads' copies. A __syncthreads() is required between
// wait and compute (as in the proven R14). 2-stage pipeline therefore uses
// two barriers per tile:
//   wait_group -> sync (all threads' kt t landed) -> compute stage t&1
//   -> sync (stage free) -> refill kt t+2 into stage t&1.
// A reads use 8KB half-blocks of the 128-row g_x blocks (sw128 only modifies
// bits 4-6 from bits 7-9, so a 64-row slice at half*8192 is self-consistent).
// ldmatrix addressing: row = lane&15, half = (lane>>4)*16, xor = (lane&7)<<4.
// B pair for n8 block nt of quad q[nt>>1]: {q[nt&1], q[(nt&1)+2]}.
// ---------------------------------------------------------------------------
__global__ __launch_bounds__(128, 4)
void gemm_kernel(float* __restrict__ out, const float* __restrict__ scaler) {
    extern __shared__ __align__(1024) char smem[];
    uint32_t sbase = smem_u32(smem);
    int tid = threadIdx.x, lane = tid & 31, wid = tid >> 5;
    int n_tile = blockIdx.x & 31, m_tile = blockIdx.x >> 5;   // n fastest: W stays L2-hot
    int warp_m = wid & 1, warp_n = wid >> 1;

    ((float*)(smem + OFF_SCAL))[tid] = scaler[n_tile * 128 + tid];

    // A: 64-row slice = half of a 128-row block.
    const char* gA = (const char*)g_x
                   + (size_t)(m_tile >> 1) * 64 * B_BLK_BYTES
                   + (size_t)(m_tile & 1) * A_SLICE_BYTES;
    const char* gB = (const char*)g_w + (size_t)n_tile * B_BLK_BYTES;

    int r16 = lane & 15;
    uint32_t bytesel = (uint32_t)((lane >> 4) * 16);
    uint32_t rxor    = (uint32_t)((lane & 7) << 4);
    uint32_t a_off[2], b_off[4];
#pragma unroll
    for (int mt = 0; mt < 2; mt++)
        a_off[mt] = (uint32_t)((warp_m * 32 + mt * 16 + r16) * 128);
#pragma unroll
    for (int p = 0; p < 4; p++)
        b_off[p] = (uint32_t)((warp_n * 64 + p * 16 + r16) * 128);

    float c[2][8][4];
#pragma unroll
    for (int mt = 0; mt < 2; mt++)
#pragma unroll
        for (int nt = 0; nt < 8; nt++)
#pragma unroll
            for (int j = 0; j < 4; j++) c[mt][nt][j] = 0.f;

    auto load_stage = [&](int s, int kt) {
        uint32_t dst = sbase + (uint32_t)s * STAGE_BYTES;
        const char* sA = gA + (size_t)kt * B_BLK_BYTES;       // kt stride = full block
        const char* sB = gB + (size_t)kt * (32 * B_BLK_BYTES);
#pragma unroll
        for (int r = 0; r < 4; r++) {                          // A: 8KB
            uint32_t off = (uint32_t)((r * 128 + tid) * 16);
            cp16(dst + off, sA + off);
        }
#pragma unroll
        for (int r = 0; r < 8; r++) {                          // B: 16KB
            uint32_t off = (uint32_t)((r * 128 + tid) * 16);
            cp16(dst + A_SLICE_BYTES + off, sB + off);
        }
        asm volatile("cp.async.commit_group;" ::: "memory");
    };

    load_stage(0, 0);
    load_stage(1, 1);            // pending = {kt0, kt1}

    for (int t = 0; t < K_TILES; t++) {
        // pending (this thread) = {kt t, kt t+1} or {kt t} at the tail.
        if (t < K_TILES - 1)
            asm volatile("cp.async.wait_group 1;" ::: "memory");  // own kt-t copies done
        else
            asm volatile("cp.async.wait_group 0;" ::: "memory");
        __syncthreads();             // ALL threads' kt-t copies landed + visible

        uint32_t st = sbase + (uint32_t)(t & 1) * STAGE_BYTES;
        uint32_t aBs = st, bBs = st + A_SLICE_BYTES;
#pragma unroll
        for (int k16 = 0; k16 < 4; k16++) {
            uint32_t low = ((uint32_t)(k16 * 32) | bytesel) ^ rxor;
            uint32_t q[4][4];
#pragma unroll
            for (int p = 0; p < 4; p++) ldsm4(q[p], bBs + b_off[p] + low);
            uint32_t ah[2][4];
#pragma unroll
            for (int mt = 0; mt < 2; mt++) ldsm4(ah[mt], aBs + a_off[mt] + low);
#pragma unroll
            for (int mt = 0; mt < 2; mt++)
#pragma unroll
                for (int nt = 0; nt < 8; nt++)
                    mma16816(c[mt][nt], ah[mt],
                             q[nt >> 1][nt & 1], q[nt >> 1][(nt & 1) + 2]);
        }

        __syncthreads();             // all 4 warps done reading stage t&1
        if (t + 2 < K_TILES) load_stage(t & 1, t + 2);   // refill freed stage
    }

    // Epilogue: scale by per-output-channel weight_scaler, write fp32
    const float* scl = (const float*)(smem + OFF_SCAL);
    int lr = lane >> 2, lc = (lane & 3) * 2;
#pragma unroll
    for (int mt = 0; mt < 2; mt++) {
        int row = m_tile * 64 + warp_m * 32 + mt * 16 + lr;
#pragma unroll
        for (int nt = 0; nt < 8; nt++) {
            int cloc = warp_n * 64 + nt * 8 + lc;
            float s0 = scl[cloc], s1 = scl[cloc + 1];
            size_t g0 = (size_t)row * N_DIM + (size_t)(n_tile * 128 + cloc);
            float2 v0 = make_float2(c[mt][nt][0] * s0, c[mt][nt][1] * s1);
            float2 v1 = make_float2(c[mt][nt][2] * s0, c[mt][nt][3] * s1);
            *(float2*)(out + g0)                     = v0;
            *(float2*)(out + g0 + 8 * (size_t)N_DIM) = v1;
        }
    }
}

// ---------------------------------------------------------------------------
extern "C" void kernel_launch(void* const* d_in, const int* in_sizes, int n_in,
                              void* d_out, int out_size) {
    // Size-based input resolution: x 33554432, weight 16777216, scaler 4096
    const float* x  = 0;
    const int*   w  = 0;
    const float* ws = 0;
    for (int i = 0; i < n_in; i++) {
        if (in_sizes[i] == 33554432)      x  = (const float*)d_in[i];
        else if (in_sizes[i] == 16777216) w  = (const int*)d_in[i];
        else if (in_sizes[i] == 4096)     ws = (const float*)d_in[i];
    }
    float* o = (float*)d_out;

    cudaFuncSetAttribute(gemm_kernel, cudaFuncAttributeMaxDynamicSharedMemorySize, SMEM_BYTES);

    conv_all_kernel<<<20480, 256>>>(w, x);
    gemm_kernel<<<M_TILES * N_TILES, 128, SMEM_BYTES>>>(o, ws);
}